// round 8
// baseline (speedup 1.0000x reference)
#include <cuda_runtime.h>
#include <cuda_fp16.h>
#include <stdint.h>

// ---------------------------------------------------------------------------
// HashEncoder (Instant-NGP multires hash grid): B=2097152 pts, D=3, L=16, C=2
// base_res=16, desired=2048, log2_hashmap=19.
//
// Level table (offsets sum to TOTAL_PARAMS = 6098120):
//   res : 16 23 31 43 59 | 81 112 154 213 295 407 562 777 1073 1483 2048
//   l<5 dense (res^3 aligned to 8), l>=5 hashed with hmap = 2^19.
//
// R6: ALL gathers go to the fp16x2 shadow table (24.4 MB random working set,
// was 72 MB mixed f32+fp16). Paired x-duo (idx1==idx0^1, ~50%): one aligned
// 8B load. Unpaired: two 4B loads. Cache-policy partition: hash levels use
// L1::no_allocate (they can't hit L1 anyway), dense levels use L1::evict_last
// (1.3 MB fp16 -> L1-resident) => dense levels stop generating L2 sector
// fills and hash streams stop evicting them.
// ---------------------------------------------------------------------------

#define NLEV 16
#define BLOCK 256
#define PTS_PER_BLK 32            // 8 threads per point, 2 levels per thread
#define TOTAL_PARAMS 6098120

__constant__ uint32_t c_res[NLEV] = {
    16u, 23u, 31u, 43u, 59u, 81u, 112u, 154u,
    213u, 295u, 407u, 562u, 777u, 1073u, 1483u, 2048u
};
__constant__ uint32_t c_off[NLEV] = {
    0u, 4096u, 16264u, 46056u, 125568u, 330952u, 855240u, 1379528u,
    1903816u, 2428104u, 2952392u, 3476680u, 4000968u, 4525256u, 5049544u, 5573832u
};

__device__ float g_scales[NLEV];
// fp16x2 shadow of the embedding table (one uint32 per entry), 24.4 MB static.
__device__ __align__(128) uint32_t g_half[TOTAL_PARAMS];

// Convert f32 table -> fp16x2 shadow; block 0 also computes per-level scales
// (double precision, matches numpy exp2(l*(7/15))*16-1 bit-for-bit).
__global__ __launch_bounds__(256)
void convert_kernel(const float4* __restrict__ emb4) {
    if (blockIdx.x == 0 && threadIdx.x < NLEV) {
        double s = exp2((double)threadIdx.x * (7.0 / 15.0)) * 16.0 - 1.0;
        g_scales[threadIdx.x] = (float)s;
    }
    int i = blockIdx.x * blockDim.x + threadIdx.x;   // pair index
    if (i < TOTAL_PARAMS / 2) {
        float4 e = emb4[i];                          // entries 2i, 2i+1
        __half2 h0 = __floats2half2_rn(e.x, e.y);
        __half2 h1 = __floats2half2_rn(e.z, e.w);
        uint32_t w0 = *(uint32_t*)&h0;
        uint32_t w1 = *(uint32_t*)&h1;
        *(uint64_t*)&g_half[2 * i] = ((uint64_t)w1 << 32) | w0;
    }
}

// All-fp16 pair-gather, hash flavor (L1::no_allocate): if pr (b == a^1), one
// aligned 8B load fetches both corners; else two 4B loads. True predication.
__device__ __forceinline__ void pair_gather_h(const uint32_t* __restrict__ tabh,
                                              uint32_t a, uint32_t b,
                                              float2& ea, float2& eb)
{
    const unsigned pr = (b == (a ^ 1u)) ? 1u : 0u;
    const uint32_t* ph = tabh + (a & ~1u);   // 8B-aligned (offsets all even)
    const uint32_t* pa = tabh + a;
    const uint32_t* pb = tabh + b;
    unsigned long long hp;
    uint32_t ua, ub;
    asm volatile(
        "{\n\t"
        ".reg .pred p;\n\t"
        "setp.ne.u32 p, %3, 0;\n\t"
        "mov.u64 %0, 0;\n\t"
        "mov.u32 %1, 0;\n\t"
        "mov.u32 %2, 0;\n\t"
        "@p  ld.global.nc.L1::no_allocate.u64 %0, [%4];\n\t"
        "@!p ld.global.nc.L1::no_allocate.u32 %1, [%5];\n\t"
        "@!p ld.global.nc.L1::no_allocate.u32 %2, [%6];\n\t"
        "}"
        : "=l"(hp), "=r"(ua), "=r"(ub)
        : "r"(pr), "l"(ph), "l"(pa), "l"(pb));
    uint32_t wa, wb;
    if (pr) {
        const uint32_t lo = (uint32_t)hp;          // entry a&~1 (even)
        const uint32_t hi = (uint32_t)(hp >> 32);  // entry a|1  (odd)
        const bool odd = (a & 1u) != 0u;
        wa = odd ? hi : lo;
        wb = odd ? lo : hi;
    } else {
        wa = ua;
        wb = ub;
    }
    ea = __half22float2(*(const __half2*)&wa);
    eb = __half22float2(*(const __half2*)&wb);
}

// Dense flavor (L1::evict_last -> stays L1-resident, tables are tiny).
__device__ __forceinline__ void pair_gather_d(const uint32_t* __restrict__ tabh,
                                              uint32_t a, uint32_t b,
                                              float2& ea, float2& eb)
{
    const unsigned pr = (b == (a ^ 1u)) ? 1u : 0u;
    const uint32_t* ph = tabh + (a & ~1u);
    const uint32_t* pa = tabh + a;
    const uint32_t* pb = tabh + b;
    unsigned long long hp;
    uint32_t ua, ub;
    asm volatile(
        "{\n\t"
        ".reg .pred p;\n\t"
        "setp.ne.u32 p, %3, 0;\n\t"
        "mov.u64 %0, 0;\n\t"
        "mov.u32 %1, 0;\n\t"
        "mov.u32 %2, 0;\n\t"
        "@p  ld.global.nc.L1::evict_last.u64 %0, [%4];\n\t"
        "@!p ld.global.nc.L1::evict_last.u32 %1, [%5];\n\t"
        "@!p ld.global.nc.L1::evict_last.u32 %2, [%6];\n\t"
        "}"
        : "=l"(hp), "=r"(ua), "=r"(ub)
        : "r"(pr), "l"(ph), "l"(pa), "l"(pb));
    uint32_t wa, wb;
    if (pr) {
        const uint32_t lo = (uint32_t)hp;
        const uint32_t hi = (uint32_t)(hp >> 32);
        const bool odd = (a & 1u) != 0u;
        wa = odd ? hi : lo;
        wb = odd ? lo : hi;
    } else {
        wa = ua;
        wb = ub;
    }
    ea = __half22float2(*(const __half2*)&wa);
    eb = __half22float2(*(const __half2*)&wb);
}

__global__ __launch_bounds__(BLOCK)
void hash_encode_kernel(const float* __restrict__ inputs,
                        float4* __restrict__ out,
                        int npts)
{
    __shared__ float s_in[PTS_PER_BLK * 3];
    __shared__ float s_scale[NLEV];

    const int tid = threadIdx.x;
    {
        int gidx = blockIdx.x * (PTS_PER_BLK * 3) + tid;
        if (tid < PTS_PER_BLK * 3 && gidx < npts * 3)
            s_in[tid] = inputs[gidx];
        if (tid < NLEV)
            s_scale[tid] = g_scales[tid];
    }
    __syncthreads();

    const int p = tid >> 3;       // point within block (0..31)
    const int s = tid & 7;        // sub-thread: handles levels 2s, 2s+1
    const long long point = (long long)blockIdx.x * PTS_PER_BLK + p;
    if (point >= npts) return;

    const float x = s_in[p * 3 + 0];
    const float y = s_in[p * 3 + 1];
    const float z = s_in[p * 3 + 2];

    float4 r;

    #pragma unroll
    for (int i = 0; i < 2; ++i) {
        const int l = (s << 1) + i;
        const float scale  = s_scale[l];
        const uint32_t res = c_res[l];
        const uint32_t* __restrict__ tabh = g_half + c_off[l];

        // pos = x*scale + 0.5, NO fma contraction (floor must match reference).
        const float posx = __fadd_rn(__fmul_rn(x, scale), 0.5f);
        const float posy = __fadd_rn(__fmul_rn(y, scale), 0.5f);
        const float posz = __fadd_rn(__fmul_rn(z, scale), 0.5f);
        const float fx = floorf(posx), fy = floorf(posy), fz = floorf(posz);
        const float tx = posx - fx,  ty = posy - fy,  tz = posz - fz;
        const uint32_t gx = (uint32_t)fx, gy = (uint32_t)fy, gz = (uint32_t)fz;
        const uint32_t rm1 = res - 1u;
        const uint32_t x0 = min(gx,      rm1), x1 = min(gx + 1u, rm1);
        const uint32_t y0 = min(gy,      rm1), y1 = min(gy + 1u, rm1);
        const uint32_t z0 = min(gz,      rm1), z1 = min(gz + 1u, rm1);

        // 4 x-pairs; pair q has (y,z) bits (q&1, q>>1).
        float2 ea[4], eb[4];
        if (l >= 5) {
            const uint32_t hy0 = y0 * 2654435761u, hy1 = y1 * 2654435761u;
            const uint32_t hz0 = z0 * 805459861u,  hz1 = z1 * 805459861u;
            const uint32_t m = 0x7FFFFu;
            uint32_t ia[4], ib[4];
            ia[0] = (x0 ^ hy0 ^ hz0) & m;  ib[0] = (x1 ^ hy0 ^ hz0) & m;
            ia[1] = (x0 ^ hy1 ^ hz0) & m;  ib[1] = (x1 ^ hy1 ^ hz0) & m;
            ia[2] = (x0 ^ hy0 ^ hz1) & m;  ib[2] = (x1 ^ hy0 ^ hz1) & m;
            ia[3] = (x0 ^ hy1 ^ hz1) & m;  ib[3] = (x1 ^ hy1 ^ hz1) & m;
            #pragma unroll
            for (int q = 0; q < 4; ++q)
                pair_gather_h(tabh, ia[q], ib[q], ea[q], eb[q]);
        } else {
            const uint32_t r2  = res * res;
            const uint32_t by0 = y0 * res, by1 = y1 * res;
            const uint32_t bz0 = z0 * r2,  bz1 = z1 * r2;
            uint32_t ia[4], ib[4];
            ia[0] = x0 + by0 + bz0;  ib[0] = x1 + by0 + bz0;
            ia[1] = x0 + by1 + bz0;  ib[1] = x1 + by1 + bz0;
            ia[2] = x0 + by0 + bz1;  ib[2] = x1 + by0 + bz1;
            ia[3] = x0 + by1 + bz1;  ib[3] = x1 + by1 + bz1;
            #pragma unroll
            for (int q = 0; q < 4; ++q)
                pair_gather_d(tabh, ia[q], ib[q], ea[q], eb[q]);
        }

        const float wx0 = 1.0f - tx, wy0 = 1.0f - ty, wz0 = 1.0f - tz;
        float a0 = 0.0f, a1 = 0.0f;
        #pragma unroll
        for (int q = 0; q < 4; ++q) {
            const float wy = (q & 1) ? ty : wy0;
            const float wz = (q & 2) ? tz : wz0;
            const float wyz = __fmul_rn(wy, wz);
            const float wa  = __fmul_rn(wx0, wyz);
            const float wb  = __fmul_rn(tx,  wyz);
            a0 = fmaf(wa, ea[q].x, a0);
            a1 = fmaf(wa, ea[q].y, a1);
            a0 = fmaf(wb, eb[q].x, a0);
            a1 = fmaf(wb, eb[q].y, a1);
        }
        if (i == 0) { r.x = a0; r.y = a1; }
        else        { r.z = a0; r.w = a1; }
    }

    // Warp = 4 points x 8 subthreads -> 512B contiguous store, fully coalesced.
    out[point * 8 + s] = r;
}

extern "C" void kernel_launch(void* const* d_in, const int* in_sizes, int n_in,
                              void* d_out, int out_size)
{
    const float*  inputs = (const float*)d_in[0];
    const float2* emb    = (const float2*)d_in[1];
    float4*       out    = (float4*)d_out;

    const int npts = in_sizes[0] / 3;

    const int npairs = TOTAL_PARAMS / 2;
    convert_kernel<<<(npairs + 255) / 256, 256>>>((const float4*)emb);

    const int total_threads = npts * 8;
    const int nblocks = (total_threads + BLOCK - 1) / BLOCK;
    hash_encode_kernel<<<nblocks, BLOCK>>>(inputs, out, npts);
}

// round 9
// speedup vs baseline: 1.4175x; 1.4175x over previous
#include <cuda_runtime.h>
#include <cuda_fp16.h>
#include <stdint.h>

// ---------------------------------------------------------------------------
// HashEncoder (Instant-NGP multires hash grid): B=2097152 pts, D=3, L=16, C=2
// base_res=16, desired=2048, log2_hashmap=19.
//
// Level table (offsets sum to TOTAL_PARAMS = 6098120):
//   res : 16 23 31 43 59 | 81 112 154 213 295 407 562 777 1073 1483 2048
//   l<5 dense (res^3 aligned to 8), l>=5 hashed with hmap = 2^19.
//
// R7: ALL gathers from the fp16x2 shadow table (24.4 MB working set), plain
// ld.global.nc (NO L1 policy hints — R6 showed L1::no_allocate also kills L2
// residency on sm_103a: DRAM went 6.7%->58.3%, +190us). Paired x-duo
// (idx1==idx0^1, ~50%): one aligned 8B load for both corners. Unpaired: two
// 4B loads.
// ---------------------------------------------------------------------------

#define NLEV 16
#define BLOCK 256
#define PTS_PER_BLK 32            // 8 threads per point, 2 levels per thread
#define TOTAL_PARAMS 6098120

__constant__ uint32_t c_res[NLEV] = {
    16u, 23u, 31u, 43u, 59u, 81u, 112u, 154u,
    213u, 295u, 407u, 562u, 777u, 1073u, 1483u, 2048u
};
__constant__ uint32_t c_off[NLEV] = {
    0u, 4096u, 16264u, 46056u, 125568u, 330952u, 855240u, 1379528u,
    1903816u, 2428104u, 2952392u, 3476680u, 4000968u, 4525256u, 5049544u, 5573832u
};

__device__ float g_scales[NLEV];
// fp16x2 shadow of the embedding table (one uint32 per entry), 24.4 MB static.
__device__ __align__(128) uint32_t g_half[TOTAL_PARAMS];

// Convert f32 table -> fp16x2 shadow; block 0 also computes per-level scales
// (double precision, matches numpy exp2(l*(7/15))*16-1).
__global__ __launch_bounds__(256)
void convert_kernel(const float4* __restrict__ emb4) {
    if (blockIdx.x == 0 && threadIdx.x < NLEV) {
        double s = exp2((double)threadIdx.x * (7.0 / 15.0)) * 16.0 - 1.0;
        g_scales[threadIdx.x] = (float)s;
    }
    int i = blockIdx.x * blockDim.x + threadIdx.x;   // pair index
    if (i < TOTAL_PARAMS / 2) {
        float4 e = emb4[i];                          // entries 2i, 2i+1
        __half2 h0 = __floats2half2_rn(e.x, e.y);
        __half2 h1 = __floats2half2_rn(e.z, e.w);
        uint32_t w0 = *(uint32_t*)&h0;
        uint32_t w1 = *(uint32_t*)&h1;
        *(uint64_t*)&g_half[2 * i] = ((uint64_t)w1 << 32) | w0;
    }
}

// All-fp16 pair-gather: if pr (b == a^1), one aligned 8B load fetches both
// corners; else two 4B loads. True predication, outputs pre-zeroed.
__device__ __forceinline__ void pair_gather(const uint32_t* __restrict__ tabh,
                                            uint32_t a, uint32_t b,
                                            float2& ea, float2& eb)
{
    const unsigned pr = (b == (a ^ 1u)) ? 1u : 0u;
    const uint32_t* ph = tabh + (a & ~1u);   // 8B-aligned (offsets all even)
    const uint32_t* pa = tabh + a;
    const uint32_t* pb = tabh + b;
    unsigned long long hp;
    uint32_t ua, ub;
    asm volatile(
        "{\n\t"
        ".reg .pred p;\n\t"
        "setp.ne.u32 p, %3, 0;\n\t"
        "mov.u64 %0, 0;\n\t"
        "mov.u32 %1, 0;\n\t"
        "mov.u32 %2, 0;\n\t"
        "@p  ld.global.nc.u64 %0, [%4];\n\t"
        "@!p ld.global.nc.u32 %1, [%5];\n\t"
        "@!p ld.global.nc.u32 %2, [%6];\n\t"
        "}"
        : "=l"(hp), "=r"(ua), "=r"(ub)
        : "r"(pr), "l"(ph), "l"(pa), "l"(pb));
    uint32_t wa, wb;
    if (pr) {
        const uint32_t lo = (uint32_t)hp;          // entry a&~1 (even)
        const uint32_t hi = (uint32_t)(hp >> 32);  // entry a|1  (odd)
        const bool odd = (a & 1u) != 0u;
        wa = odd ? hi : lo;
        wb = odd ? lo : hi;
    } else {
        wa = ua;
        wb = ub;
    }
    ea = __half22float2(*(const __half2*)&wa);
    eb = __half22float2(*(const __half2*)&wb);
}

__global__ __launch_bounds__(BLOCK)
void hash_encode_kernel(const float* __restrict__ inputs,
                        float4* __restrict__ out,
                        int npts)
{
    __shared__ float s_in[PTS_PER_BLK * 3];
    __shared__ float s_scale[NLEV];

    const int tid = threadIdx.x;
    {
        int gidx = blockIdx.x * (PTS_PER_BLK * 3) + tid;
        if (tid < PTS_PER_BLK * 3 && gidx < npts * 3)
            s_in[tid] = inputs[gidx];
        if (tid < NLEV)
            s_scale[tid] = g_scales[tid];
    }
    __syncthreads();

    const int p = tid >> 3;       // point within block (0..31)
    const int s = tid & 7;        // sub-thread: handles levels 2s, 2s+1
    const long long point = (long long)blockIdx.x * PTS_PER_BLK + p;
    if (point >= npts) return;

    const float x = s_in[p * 3 + 0];
    const float y = s_in[p * 3 + 1];
    const float z = s_in[p * 3 + 2];

    float4 r;

    #pragma unroll
    for (int i = 0; i < 2; ++i) {
        const int l = (s << 1) + i;
        const float scale  = s_scale[l];
        const uint32_t res = c_res[l];
        const uint32_t* __restrict__ tabh = g_half + c_off[l];

        // pos = x*scale + 0.5, NO fma contraction (floor must match reference).
        const float posx = __fadd_rn(__fmul_rn(x, scale), 0.5f);
        const float posy = __fadd_rn(__fmul_rn(y, scale), 0.5f);
        const float posz = __fadd_rn(__fmul_rn(z, scale), 0.5f);
        const float fx = floorf(posx), fy = floorf(posy), fz = floorf(posz);
        const float tx = posx - fx,  ty = posy - fy,  tz = posz - fz;
        const uint32_t gx = (uint32_t)fx, gy = (uint32_t)fy, gz = (uint32_t)fz;
        const uint32_t rm1 = res - 1u;
        const uint32_t x0 = min(gx,      rm1), x1 = min(gx + 1u, rm1);
        const uint32_t y0 = min(gy,      rm1), y1 = min(gy + 1u, rm1);
        const uint32_t z0 = min(gz,      rm1), z1 = min(gz + 1u, rm1);

        // 4 x-pairs; pair q has (y,z) bits (q&1, q>>1).
        uint32_t ia[4], ib[4];
        if (l >= 5) {
            const uint32_t hy0 = y0 * 2654435761u, hy1 = y1 * 2654435761u;
            const uint32_t hz0 = z0 * 805459861u,  hz1 = z1 * 805459861u;
            const uint32_t m = 0x7FFFFu;
            ia[0] = (x0 ^ hy0 ^ hz0) & m;  ib[0] = (x1 ^ hy0 ^ hz0) & m;
            ia[1] = (x0 ^ hy1 ^ hz0) & m;  ib[1] = (x1 ^ hy1 ^ hz0) & m;
            ia[2] = (x0 ^ hy0 ^ hz1) & m;  ib[2] = (x1 ^ hy0 ^ hz1) & m;
            ia[3] = (x0 ^ hy1 ^ hz1) & m;  ib[3] = (x1 ^ hy1 ^ hz1) & m;
        } else {
            const uint32_t r2  = res * res;
            const uint32_t by0 = y0 * res, by1 = y1 * res;
            const uint32_t bz0 = z0 * r2,  bz1 = z1 * r2;
            ia[0] = x0 + by0 + bz0;  ib[0] = x1 + by0 + bz0;
            ia[1] = x0 + by1 + bz0;  ib[1] = x1 + by1 + bz0;
            ia[2] = x0 + by0 + bz1;  ib[2] = x1 + by0 + bz1;
            ia[3] = x0 + by1 + bz1;  ib[3] = x1 + by1 + bz1;
        }

        float2 ea[4], eb[4];
        #pragma unroll
        for (int q = 0; q < 4; ++q)
            pair_gather(tabh, ia[q], ib[q], ea[q], eb[q]);

        const float wx0 = 1.0f - tx, wy0 = 1.0f - ty, wz0 = 1.0f - tz;
        float a0 = 0.0f, a1 = 0.0f;
        #pragma unroll
        for (int q = 0; q < 4; ++q) {
            const float wy = (q & 1) ? ty : wy0;
            const float wz = (q & 2) ? tz : wz0;
            const float wyz = __fmul_rn(wy, wz);
            const float wa  = __fmul_rn(wx0, wyz);
            const float wb  = __fmul_rn(tx,  wyz);
            a0 = fmaf(wa, ea[q].x, a0);
            a1 = fmaf(wa, ea[q].y, a1);
            a0 = fmaf(wb, eb[q].x, a0);
            a1 = fmaf(wb, eb[q].y, a1);
        }
        if (i == 0) { r.x = a0; r.y = a1; }
        else        { r.z = a0; r.w = a1; }
    }

    // Warp = 4 points x 8 subthreads -> 512B contiguous store, fully coalesced.
    out[point * 8 + s] = r;
}

extern "C" void kernel_launch(void* const* d_in, const int* in_sizes, int n_in,
                              void* d_out, int out_size)
{
    const float*  inputs = (const float*)d_in[0];
    const float2* emb    = (const float2*)d_in[1];
    float4*       out    = (float4*)d_out;

    const int npts = in_sizes[0] / 3;

    const int npairs = TOTAL_PARAMS / 2;
    convert_kernel<<<(npairs + 255) / 256, 256>>>((const float4*)emb);

    const int total_threads = npts * 8;
    const int nblocks = (total_threads + BLOCK - 1) / BLOCK;
    hash_encode_kernel<<<nblocks, BLOCK>>>(inputs, out, npts);
}

// round 10
// speedup vs baseline: 1.5202x; 1.0724x over previous
#include <cuda_runtime.h>
#include <cuda_fp16.h>
#include <stdint.h>

// ---------------------------------------------------------------------------
// HashEncoder (Instant-NGP multires hash grid): B=2097152 pts, D=3, L=16, C=2
// base_res=16, desired=2048, log2_hashmap=19.
//
// Level table (offsets sum to TOTAL_PARAMS = 6098120):
//   res : 16 23 31 43 59 | 81 112 154 213 295 407 562 777 1073 1483 2048
//   l<5 dense (res^3 aligned to 8), l>=5 hashed with hmap = 2^19.
//
// R8: all-fp16 gathers (24.4 MB shadow), plain ld.global.nc (no L1 hints —
// they kill L2 residency on sm_103a). Hash levels: paired x-duo = one aligned
// 8B load (~50%), else two 4B loads. Dense levels: duplicated pair table
// g_dup[i] = (h[i], h[i+1]) so EVERY pair is exactly one 8B load.
// Lane-loads/point: 11*6 + 5*4 = 86 (was 96).
// ---------------------------------------------------------------------------

#define NLEV 16
#define BLOCK 256
#define PTS_PER_BLK 32            // 8 threads per point, 2 levels per thread
#define TOTAL_PARAMS 6098120
#define DENSE_PARAMS 330952       // OFFSETS[5]: entries of dense levels 0-4

__constant__ uint32_t c_res[NLEV] = {
    16u, 23u, 31u, 43u, 59u, 81u, 112u, 154u,
    213u, 295u, 407u, 562u, 777u, 1073u, 1483u, 2048u
};
__constant__ uint32_t c_off[NLEV] = {
    0u, 4096u, 16264u, 46056u, 125568u, 330952u, 855240u, 1379528u,
    1903816u, 2428104u, 2952392u, 3476680u, 4000968u, 4525256u, 5049544u, 5573832u
};

__device__ float g_scales[NLEV];
// fp16x2 shadow of the whole embedding table (one uint32 per entry), 24.4 MB.
__device__ __align__(128) uint32_t g_half[TOTAL_PARAMS];
// Duplicated pair table for dense levels: g_dup[i] = (half[i], half[i+1]).
__device__ __align__(128) unsigned long long g_dup[DENSE_PARAMS];

// Convert f32 table -> fp16x2 shadow; block 0 also computes per-level scales.
__global__ __launch_bounds__(256)
void convert_kernel(const float4* __restrict__ emb4) {
    if (blockIdx.x == 0 && threadIdx.x < NLEV) {
        double s = exp2((double)threadIdx.x * (7.0 / 15.0)) * 16.0 - 1.0;
        g_scales[threadIdx.x] = (float)s;
    }
    int i = blockIdx.x * blockDim.x + threadIdx.x;   // pair index
    if (i < TOTAL_PARAMS / 2) {
        float4 e = emb4[i];                          // entries 2i, 2i+1
        __half2 h0 = __floats2half2_rn(e.x, e.y);
        __half2 h1 = __floats2half2_rn(e.z, e.w);
        uint32_t w0 = *(uint32_t*)&h0;
        uint32_t w1 = *(uint32_t*)&h1;
        *(uint64_t*)&g_half[2 * i] = ((uint64_t)w1 << 32) | w0;
    }
}

// Build dense dup table straight from the f32 source (no dependence on g_half).
__global__ __launch_bounds__(256)
void dense_dup_kernel(const float2* __restrict__ emb) {
    int i = blockIdx.x * blockDim.x + threadIdx.x;
    if (i < DENSE_PARAMS) {
        float2 e0 = emb[i];
        float2 e1 = emb[i + 1];   // i+1 <= DENSE_PARAMS < TOTAL_PARAMS: in-bounds
        __half2 h0 = __floats2half2_rn(e0.x, e0.y);
        __half2 h1 = __floats2half2_rn(e1.x, e1.y);
        uint32_t w0 = *(uint32_t*)&h0;
        uint32_t w1 = *(uint32_t*)&h1;
        g_dup[i] = ((unsigned long long)w1 << 32) | w0;
    }
}

// Hash-level pair-gather: if pr (b == a^1), one aligned 8B load fetches both
// corners; else two 4B loads. True predication, outputs pre-zeroed.
__device__ __forceinline__ void pair_gather(const uint32_t* __restrict__ tabh,
                                            uint32_t a, uint32_t b,
                                            float2& ea, float2& eb)
{
    const unsigned pr = (b == (a ^ 1u)) ? 1u : 0u;
    const uint32_t* ph = tabh + (a & ~1u);   // 8B-aligned (offsets all even)
    const uint32_t* pa = tabh + a;
    const uint32_t* pb = tabh + b;
    unsigned long long hp;
    uint32_t ua, ub;
    asm volatile(
        "{\n\t"
        ".reg .pred p;\n\t"
        "setp.ne.u32 p, %3, 0;\n\t"
        "mov.u64 %0, 0;\n\t"
        "mov.u32 %1, 0;\n\t"
        "mov.u32 %2, 0;\n\t"
        "@p  ld.global.nc.u64 %0, [%4];\n\t"
        "@!p ld.global.nc.u32 %1, [%5];\n\t"
        "@!p ld.global.nc.u32 %2, [%6];\n\t"
        "}"
        : "=l"(hp), "=r"(ua), "=r"(ub)
        : "r"(pr), "l"(ph), "l"(pa), "l"(pb));
    uint32_t wa, wb;
    if (pr) {
        const uint32_t lo = (uint32_t)hp;          // entry a&~1 (even)
        const uint32_t hi = (uint32_t)(hp >> 32);  // entry a|1  (odd)
        const bool odd = (a & 1u) != 0u;
        wa = odd ? hi : lo;
        wb = odd ? lo : hi;
    } else {
        wa = ua;
        wb = ub;
    }
    ea = __half22float2(*(const __half2*)&wa);
    eb = __half22float2(*(const __half2*)&wb);
}

__global__ __launch_bounds__(BLOCK)
void hash_encode_kernel(const float* __restrict__ inputs,
                        float4* __restrict__ out,
                        int npts)
{
    __shared__ float s_in[PTS_PER_BLK * 3];
    __shared__ float s_scale[NLEV];

    const int tid = threadIdx.x;
    {
        int gidx = blockIdx.x * (PTS_PER_BLK * 3) + tid;
        if (tid < PTS_PER_BLK * 3 && gidx < npts * 3)
            s_in[tid] = inputs[gidx];
        if (tid < NLEV)
            s_scale[tid] = g_scales[tid];
    }
    __syncthreads();

    const int p = tid >> 3;       // point within block (0..31)
    const int s = tid & 7;        // sub-thread: handles levels 2s, 2s+1
    const long long point = (long long)blockIdx.x * PTS_PER_BLK + p;
    if (point >= npts) return;

    const float x = s_in[p * 3 + 0];
    const float y = s_in[p * 3 + 1];
    const float z = s_in[p * 3 + 2];

    float4 r;

    #pragma unroll
    for (int i = 0; i < 2; ++i) {
        const int l = (s << 1) + i;
        const float scale  = s_scale[l];
        const uint32_t res = c_res[l];

        // pos = x*scale + 0.5, NO fma contraction (floor must match reference).
        const float posx = __fadd_rn(__fmul_rn(x, scale), 0.5f);
        const float posy = __fadd_rn(__fmul_rn(y, scale), 0.5f);
        const float posz = __fadd_rn(__fmul_rn(z, scale), 0.5f);
        const float fx = floorf(posx), fy = floorf(posy), fz = floorf(posz);
        const float tx = posx - fx,  ty = posy - fy,  tz = posz - fz;
        const uint32_t gx = (uint32_t)fx, gy = (uint32_t)fy, gz = (uint32_t)fz;
        const uint32_t rm1 = res - 1u;
        const uint32_t x0 = min(gx,      rm1), x1 = min(gx + 1u, rm1);
        const uint32_t y0 = min(gy,      rm1), y1 = min(gy + 1u, rm1);
        const uint32_t z0 = min(gz,      rm1), z1 = min(gz + 1u, rm1);

        // 4 x-pairs; pair q has (y,z) bits (q&1, q>>1).
        float2 ea[4], eb[4];
        if (l >= 5) {
            const uint32_t* __restrict__ tabh = g_half + c_off[l];
            const uint32_t hy0 = y0 * 2654435761u, hy1 = y1 * 2654435761u;
            const uint32_t hz0 = z0 * 805459861u,  hz1 = z1 * 805459861u;
            const uint32_t m = 0x7FFFFu;
            uint32_t ia[4], ib[4];
            ia[0] = (x0 ^ hy0 ^ hz0) & m;  ib[0] = (x1 ^ hy0 ^ hz0) & m;
            ia[1] = (x0 ^ hy1 ^ hz0) & m;  ib[1] = (x1 ^ hy1 ^ hz0) & m;
            ia[2] = (x0 ^ hy0 ^ hz1) & m;  ib[2] = (x1 ^ hy0 ^ hz1) & m;
            ia[3] = (x0 ^ hy1 ^ hz1) & m;  ib[3] = (x1 ^ hy1 ^ hz1) & m;
            #pragma unroll
            for (int q = 0; q < 4; ++q)
                pair_gather(tabh, ia[q], ib[q], ea[q], eb[q]);
        } else {
            // Dense: dup table makes every x-pair exactly one aligned 8B load.
            // ib = ia+1 normally; ib == ia at the clamp edge (x0 == x1 == rm1).
            const unsigned long long* __restrict__ dup = g_dup + c_off[l];
            const bool bsame = (x1 == x0);
            const uint32_t r2  = res * res;
            const uint32_t by0 = y0 * res, by1 = y1 * res;
            const uint32_t bz0 = z0 * r2,  bz1 = z1 * r2;
            uint32_t ia[4];
            ia[0] = x0 + by0 + bz0;
            ia[1] = x0 + by1 + bz0;
            ia[2] = x0 + by0 + bz1;
            ia[3] = x0 + by1 + bz1;
            #pragma unroll
            for (int q = 0; q < 4; ++q) {
                const unsigned long long v = __ldg(dup + ia[q]);
                const uint32_t lo = (uint32_t)v;           // entry ia
                const uint32_t hi = (uint32_t)(v >> 32);   // entry ia+1
                const uint32_t wb = bsame ? lo : hi;
                ea[q] = __half22float2(*(const __half2*)&lo);
                eb[q] = __half22float2(*(const __half2*)&wb);
            }
        }

        const float wx0 = 1.0f - tx, wy0 = 1.0f - ty, wz0 = 1.0f - tz;
        float a0 = 0.0f, a1 = 0.0f;
        #pragma unroll
        for (int q = 0; q < 4; ++q) {
            const float wy = (q & 1) ? ty : wy0;
            const float wz = (q & 2) ? tz : wz0;
            const float wyz = __fmul_rn(wy, wz);
            const float wa  = __fmul_rn(wx0, wyz);
            const float wb  = __fmul_rn(tx,  wyz);
            a0 = fmaf(wa, ea[q].x, a0);
            a1 = fmaf(wa, ea[q].y, a1);
            a0 = fmaf(wb, eb[q].x, a0);
            a1 = fmaf(wb, eb[q].y, a1);
        }
        if (i == 0) { r.x = a0; r.y = a1; }
        else        { r.z = a0; r.w = a1; }
    }

    // Warp = 4 points x 8 subthreads -> 512B contiguous store, fully coalesced.
    out[point * 8 + s] = r;
}

extern "C" void kernel_launch(void* const* d_in, const int* in_sizes, int n_in,
                              void* d_out, int out_size)
{
    const float*  inputs = (const float*)d_in[0];
    const float2* emb    = (const float2*)d_in[1];
    float4*       out    = (float4*)d_out;

    const int npts = in_sizes[0] / 3;

    const int npairs = TOTAL_PARAMS / 2;
    convert_kernel<<<(npairs + 255) / 256, 256>>>((const float4*)emb);
    dense_dup_kernel<<<(DENSE_PARAMS + 255) / 256, 256>>>(emb);

    const int total_threads = npts * 8;
    const int nblocks = (total_threads + BLOCK - 1) / BLOCK;
    hash_encode_kernel<<<nblocks, BLOCK>>>(inputs, out, npts);
}